// round 11
// baseline (speedup 1.0000x reference)
// v11 — GEMM folded into k3 via linearity (gather in X-space, then @W once
// per row from smem). g_h eliminated. k1 = extract + ew only (no smem).
#include <cuda_runtime.h>

#define NN 1024
#define EE 1536
#define MAXDEG 64

#define FMA_F32X2(d, a, b, c) \
    asm("fma.rn.f32x2 %0, %1, %2, %3;" : "=l"(d) : "l"(a), "l"(b), "l"(c))
#define PACK_F32X2(out, lo, hi) \
    asm("mov.b64 %0, {%1, %2};" : "=l"(out) : "f"(lo), "f"(hi))
#define UNPACK_F32X2(lo, hi, in) \
    asm("mov.b64 {%0, %1}, %2;" : "=f"(lo), "=f"(hi) : "l"(in))

__device__ float g_ew[8 * EE];
__device__ int   g_slot[EE];            // exch slot (0 = empty); re-zeroed by k3
__device__ int   g_deg[NN];             // zero at load; re-zeroed by k3
__device__ int   g_adj[NN * MAXDEG];    // packed: e | (o << 11)
__device__ float g_adjw[NN * MAXDEG];   // lap[i, o]

// ---------------------------------------------------------------------------
// K1: 240 blocks x 256 threads. NO smem, NO GEMM.
//   [0,192):   extract (atomicExch edge resolve + lap prefetch), 8 f4/thread
//   [192,240): ew[b,e] = edges[b,e,:] . evec
// ---------------------------------------------------------------------------
__global__ void __launch_bounds__(256) k1(
    const float* __restrict__ edges,   // [8,1536,32]
    const float* __restrict__ evec,    // [32]
    const float* __restrict__ inc,     // [1024,1536]
    const float* __restrict__ lap)     // [1024,1024]
{
    const int bx  = blockIdx.x;
    const int tid = threadIdx.x;

    if (bx < 192) {
        // ----- extract role: 8 float4 per thread, batched loads -----
        const int t = bx * 256 + tid;                // < 49152; 8*49152=393216
        const float4* inc4 = (const float4*)inc;
        float4 v[8];
        #pragma unroll
        for (int j = 0; j < 8; j++)
            v[j] = inc4[t + j * 49152];
        #pragma unroll
        for (int j = 0; j < 8; j++) {
            int idx4 = t + j * 49152;
            float vals[4] = {v[j].x, v[j].y, v[j].z, v[j].w};
            #pragma unroll
            for (int c = 0; c < 4; c++) {
                if (vals[c] != 0.f) {
                    int idx = (idx4 << 2) + c;
                    int i = idx / EE;
                    int e = idx - i * EE;
                    int old = atomicExch(&g_slot[e], i + 1);
                    if (old != 0) {
                        int o = old - 1;
                        float lv = lap[i * NN + o];      // == lap[o*NN+i]
                        int di = atomicAdd(&g_deg[i], 1);
                        if (di < MAXDEG) {
                            g_adj[i * MAXDEG + di]  = e | (o << 11);
                            g_adjw[i * MAXDEG + di] = lv;
                        }
                        int dj = atomicAdd(&g_deg[o], 1);
                        if (dj < MAXDEG) {
                            g_adj[o * MAXDEG + dj]  = e | (i << 11);
                            g_adjw[o * MAXDEG + dj] = lv;
                        }
                    }
                }
            }
        }
        return;
    }

    // ----- ew role: 48 blocks; 4 edges per warp-iter, 8 lanes per edge -----
    {
        const int wb   = (bx - 192) * 8 + (tid >> 5);   // 0..383
        const int lane = tid & 31;
        const int sub  = lane >> 3;
        const int off  = lane & 7;
        float4 ev = ((const float4*)evec)[off];
        #pragma unroll
        for (int it = 0; it < 8; it++) {
            int e = wb * 32 + it * 4 + sub;              // < 12288
            float4 d = ((const float4*)edges)[e * 8 + off];
            float s = d.x * ev.x + d.y * ev.y + d.z * ev.z + d.w * ev.w;
            s += __shfl_xor_sync(0xffffffffu, s, 4);
            s += __shfl_xor_sync(0xffffffffu, s, 2);
            s += __shfl_xor_sync(0xffffffffu, s, 1);
            if (off == 0) g_ew[e] = s;
        }
    }
}

// ---------------------------------------------------------------------------
// K3: 512 blocks x 512 threads, 2 nodes per block.
// Phase 1 (thread = (b,k)): gather y[b,node,k] in X-space:
//   y = lap_ii*S*X[b,i,k] + sum_j lap_io*ew*X[b,o,k]   -> smem (f32x2 pair)
// Phase 2 (thread = (b,f)): out[b,{i0,i1},f] = sum_k y-pair[k] * W[k,f] (FFMA2)
// ---------------------------------------------------------------------------
__global__ void __launch_bounds__(512) k3(
    const float* __restrict__ nodes,   // [8192,64]
    const float* __restrict__ W,       // [64,64]
    const float* __restrict__ lap,
    float* __restrict__ out)
{
    __shared__ __align__(16) float sW[64 * 64];     // 16 KB
    __shared__ __align__(16) float2 syp[8][64];     // 4 KB: (y_i0, y_i1)
    __shared__ int   sse[2][MAXDEG];
    __shared__ int   sso[2][MAXDEG];
    __shared__ float ssl[2][MAXDEG];
    __shared__ int   sdeg[2];
    __shared__ float slii[2];

    const int i0  = blockIdx.x * 2;
    const int tid = threadIdx.x;

    // W -> smem (2 float4 per thread)
    ((float4*)sW)[tid]       = ((const float4*)W)[tid];
    ((float4*)sW)[tid + 512] = ((const float4*)W)[tid + 512];

    // metadata fill: one parallel L2 trip
    if (tid < 128) {
        const int g    = tid >> 6;
        const int slot = tid & 63;
        const int i    = i0 + g;
        int   d  = g_deg[i];                      // independent loads
        int   pk = g_adj[i * MAXDEG + slot];      // speculative (valid bits)
        float wv = g_adjw[i * MAXDEG + slot];
        if (d > MAXDEG) d = MAXDEG;
        if (slot == 0) { sdeg[g] = d; slii[g] = lap[i * NN + i]; }
        if (slot < d) {
            sse[g][slot] = pk & 2047;
            sso[g][slot] = pk >> 11;
            ssl[g][slot] = wv;
        }
    }
    __syncthreads();

    // resets strictly AFTER all reads of g_deg
    if (tid == 0) { g_deg[i0] = 0; g_deg[i0 + 1] = 0; }
    if (tid >= 1 && tid < 4) g_slot[blockIdx.x * 3 + (tid - 1)] = 0; // 512*3=1536

    const int b = tid >> 6;
    const int k = tid & 63;
    const float* xb  = nodes + b * 65536;
    const float* ewb = g_ew  + b * EE;

    // ---- Phase 1: X-space gather for both nodes ----
    const int d0 = sdeg[0], d1 = sdeg[1];
    float xv0 = xb[(i0 + 0) * 64 + k];
    float xv1 = xb[(i0 + 1) * 64 + k];

    float S0 = 0.f, acc0 = 0.f;
    for (int j = 0; j < d0; j++) {
        float w = ewb[sse[0][j]];
        S0   += w;
        acc0 += ssl[0][j] * w * xb[sso[0][j] * 64 + k];
    }
    float S1 = 0.f, acc1 = 0.f;
    for (int j = 0; j < d1; j++) {
        float w = ewb[sse[1][j]];
        S1   += w;
        acc1 += ssl[1][j] * w * xb[sso[1][j] * 64 + k];
    }
    syp[b][k] = make_float2(slii[0] * S0 * xv0 + acc0,
                            slii[1] * S1 * xv1 + acc1);
    __syncthreads();

    // ---- Phase 2: multiply by W (f = k index reused) ----
    const int f = k;
    unsigned long long acc = 0;
    const unsigned long long* yrow = (const unsigned long long*)&syp[b][0];
    #pragma unroll 16
    for (int kk = 0; kk < 64; kk++) {
        unsigned long long yp = yrow[kk];          // (y_i0, y_i1) broadcast
        float w = sW[kk * 64 + f];                 // coalesced 128B
        unsigned long long wp;
        PACK_F32X2(wp, w, w);
        FMA_F32X2(acc, yp, wp, acc);
    }
    float o0, o1;
    UNPACK_F32X2(o0, o1, acc);
    out[(b * NN + i0 + 0) * 64 + f] = o0;
    out[(b * NN + i0 + 1) * 64 + f] = o1;
}

// ---------------------------------------------------------------------------
extern "C" void kernel_launch(void* const* d_in, const int* in_sizes, int n_in,
                              void* d_out, int out_size)
{
    const float* nodes = (const float*)d_in[0];
    const float* edges = (const float*)d_in[1];
    const float* W     = (const float*)d_in[2];
    const float* evec  = (const float*)d_in[3];
    const float* inc   = (const float*)d_in[4];
    const float* lap   = (const float*)d_in[5];
    float* out = (float*)d_out;

    (void)in_sizes; (void)n_in; (void)out_size;

    k1<<<240, 256>>>(edges, evec, inc, lap);
    k3<<<512, 512>>>(nodes, W, lap, out);
}